// round 12
// baseline (speedup 1.0000x reference)
#include <cuda_runtime.h>
#include <cuda_fp16.h>
#include <cstdint>

#define Nn 1024
#define Tt 512
#define Hh 128
#define Gg 512
#define NTT (Nn*Tt)
#define WPAD 136

// ---------------- device scratch ----------------
__device__ __half g_xg[(size_t)NTT * Gg];     // 512 MB fp16: xg = F1 @ M^T + bxg
__device__ __half g_hcat[(size_t)NTT * 256];  // 256 MB fp16: relu(h) [row][fw128|bw128]
__device__ __half g_whh_h[512 * WPAD];        // fp16 w_hh [j][k] padded
__device__ __half g_M_h[512 * WPAD];          // fp16 M = wih@e2w  [j][h] padded
__device__ float  g_bxg[512];                 // wih @ b2
__device__ __half g_dec1h[128 * 264];         // fp16 dec1 [o][k] padded (k stride 264)

__device__ __forceinline__ float tanh_a(float x) {
    float y; asm("tanh.approx.f32 %0, %1;" : "=f"(y) : "f"(x)); return y;
}
__device__ __forceinline__ float sigm_a(float x) {
    return fmaf(tanh_a(0.5f * x), 0.5f, 0.5f);
}

__device__ __forceinline__ void cp16(void* smem_dst, const void* gsrc) {
    unsigned s = (unsigned)__cvta_generic_to_shared(smem_dst);
    asm volatile("cp.async.ca.shared.global [%0], [%1], 16;" :: "r"(s), "l"(gsrc));
}
__device__ __forceinline__ void cp_commit() { asm volatile("cp.async.commit_group;"); }
__device__ __forceinline__ void cp_wait1()  { asm volatile("cp.async.wait_group 1;"); }
__device__ __forceinline__ void cp_wait0()  { asm volatile("cp.async.wait_group 0;"); }

__device__ __forceinline__ void ldsm4(uint32_t addr, uint32_t& r0, uint32_t& r1,
                                      uint32_t& r2, uint32_t& r3) {
    asm volatile("ldmatrix.sync.aligned.m8n8.x4.shared.b16 {%0,%1,%2,%3}, [%4];"
                 : "=r"(r0), "=r"(r1), "=r"(r2), "=r"(r3) : "r"(addr));
}
__device__ __forceinline__ void mma16816(float* d, uint32_t a0, uint32_t a1, uint32_t a2,
                                         uint32_t a3, uint32_t b0, uint32_t b1) {
    asm volatile(
        "mma.sync.aligned.m16n8k16.row.col.f32.f16.f16.f32 "
        "{%0,%1,%2,%3}, {%4,%5,%6,%7}, {%8,%9}, {%0,%1,%2,%3};"
        : "+f"(d[0]), "+f"(d[1]), "+f"(d[2]), "+f"(d[3])
        : "r"(a0), "r"(a1), "r"(a2), "r"(a3), "r"(b0), "r"(b1));
}

// ---------------- K0: weight prep ----------------
__global__ void prep_kernel(const float* __restrict__ wih, const float* __restrict__ whh,
                            const float* __restrict__ e2w, const float* __restrict__ e2b,
                            const float* __restrict__ dec1) {
    int i = blockIdx.x * blockDim.x + threadIdx.x;
    if (i < 65536) {
        int j = i >> 7, h = i & 127;
        float s = 0.f;
#pragma unroll 4
        for (int o = 0; o < 128; o++) s += wih[j * 128 + o] * e2w[o * 128 + h];
        g_M_h[j * WPAD + h] = __float2half(s);
    } else if (i < 66048) {
        int j = i - 65536;
        float s = 0.f;
#pragma unroll 4
        for (int o = 0; o < 128; o++) s += e2b[o] * wih[j * 128 + o];
        g_bxg[j] = s;
    } else if (i < 135680) {
        int p = i - 66048;
        int j = p / WPAD, k = p % WPAD;
        g_whh_h[p] = (k < 128) ? __float2half(whh[j * 128 + k]) : __float2half(0.f);
    } else if (i < 169472) {
        int p = i - 135680;
        int j = p / 264, k = p % 264;
        g_dec1h[p] = (k < 256) ? __float2half(dec1[j * 256 + k]) : __float2half(0.f);
    }
}

// ---------------- K1: encoder — smem-staged coalesced g_xg writes ----------------
#define ENC_OFF_AHI 139264
#define ENC_OFF_BXG 156672
#define ENC_OFF_E1W 158720
#define ENC_OFF_E1B 159744
#define ENC_OFF_OUT 160256
#define ENC_OSTRIDE 520
#define ENC_SMEM    (ENC_OFF_OUT + 64 * ENC_OSTRIDE * 2)   // 226816
__global__ __launch_bounds__(256, 1) void encoder_kernel(
    const float* __restrict__ x, const float* __restrict__ e1w,
    const float* __restrict__ e1b) {
    extern __shared__ char smraw[];
    __half* sM   = (__half*)smraw;
    __half* sAhi = (__half*)(smraw + ENC_OFF_AHI);
    float*  sBxg = (float*)(smraw + ENC_OFF_BXG);
    float*  sE1w = (float*)(smraw + ENC_OFF_E1W);
    float*  sE1b = (float*)(smraw + ENC_OFF_E1B);
    __half* sOut = (__half*)(smraw + ENC_OFF_OUT);

    int tid = threadIdx.x, w = tid >> 5, l = tid & 31;

    for (int i = tid; i < 8704; i += 256) cp16(((uint4*)sM) + i, ((const uint4*)g_M_h) + i);
    cp_commit();
    for (int i = tid; i < 512; i += 256) sBxg[i] = g_bxg[i];
    if (tid < 256) sE1w[tid] = e1w[tid];
    if (tid < 128) sE1b[tid] = e1b[tid];
    cp_wait0();
    __syncthreads();

    const int lrow = (l & 7) + ((l >> 3) & 1) * 8;
    const int lcol = (l >> 4) * 8;
    const int jw = w * 64;
    const int g = l >> 2, tg = l & 3;
    uint32_t sMb   = (uint32_t)__cvta_generic_to_shared(sM);
    uint32_t sAhib = (uint32_t)__cvta_generic_to_shared(sAhi);

    const int fr = tid >> 2, fh0 = (tid & 3) * 32;

    for (int blk = blockIdx.x; blk < NTT / 64; blk += gridDim.x) {
        int row0 = blk * 64;
        float x0 = x[(size_t)(row0 + fr) * 2];
        float x1 = x[(size_t)(row0 + fr) * 2 + 1];
#pragma unroll
        for (int hh = 0; hh < 32; hh += 2) {
            int h = fh0 + hh;
            float v0 = fmaxf(sE1w[2 * h]     * x0 + sE1w[2 * h + 1] * x1 + sE1b[h], 0.f);
            float v1 = fmaxf(sE1w[2 * h + 2] * x0 + sE1w[2 * h + 3] * x1 + sE1b[h + 1], 0.f);
            *(__half2*)&sAhi[fr * WPAD + h] = __floats2half2_rn(v0, v1);
        }
        __syncthreads();

#pragma unroll
        for (int mt = 0; mt < 4; mt++) {
            float d[8][4];
#pragma unroll
            for (int nt = 0; nt < 8; nt++)
#pragma unroll
                for (int e = 0; e < 4; e++) d[nt][e] = 0.f;
#pragma unroll
            for (int ks = 0; ks < 8; ks++) {
                uint32_t aoff = (uint32_t)(((mt * 16 + lrow) * WPAD + ks * 16 + lcol) << 1);
                uint32_t ah0, ah1, ah2, ah3;
                ldsm4(sAhib + aoff, ah0, ah1, ah2, ah3);
#pragma unroll
                for (int np = 0; np < 4; np++) {
                    uint32_t boff = (uint32_t)(((jw + np * 16 + lrow) * WPAD + ks * 16 + lcol) << 1);
                    uint32_t b0, b1, b2, b3;
                    ldsm4(sMb + boff, b0, b1, b2, b3);
                    mma16816(d[2 * np],     ah0, ah1, ah2, ah3, b0, b2);
                    mma16816(d[2 * np + 1], ah0, ah1, ah2, ah3, b1, b3);
                }
            }
            // stage (biased) fp16 fragments into sOut — conflict-free
#pragma unroll
            for (int nt = 0; nt < 8; nt++) {
                int col = jw + nt * 8 + 2 * tg;
                float b0v = sBxg[col], b1v = sBxg[col + 1];
                *(__half2*)&sOut[(mt * 16 + g) * ENC_OSTRIDE + col] =
                    __floats2half2_rn(d[nt][0] + b0v, d[nt][1] + b1v);
                *(__half2*)&sOut[(mt * 16 + g + 8) * ENC_OSTRIDE + col] =
                    __floats2half2_rn(d[nt][2] + b0v, d[nt][3] + b1v);
            }
        }
        __syncthreads();

        // coalesced copy sOut -> g_xg (16 x STG.128 per thread)
#pragma unroll
        for (int it = 0; it < 16; it++) {
            int idx = it * 256 + tid;
            int r = idx >> 6, ck = idx & 63;
            uint4 v = *(const uint4*)&sOut[r * ENC_OSTRIDE + ck * 8];
            *(uint4*)&g_xg[(size_t)(row0 + r) * 512 + ck * 8] = v;
        }
        __syncthreads();
    }
}

// ---------------- K2: bidirectional LSTM — 512 thr, reg-resident W, split chains ----------------
#define REC_OFF_H    139264
#define REC_HBUF     4352
#define REC_OFF_XG   (REC_OFF_H + 2 * REC_HBUF)          // 147968
#define REC_XGBUF    16640
#define SXG_STRIDE   520
#define REC_OFF_RELU (REC_OFF_XG + 3 * REC_XGBUF)        // 197888
#define REC_RELUBUF  4352
#define REC_SMEM     (REC_OFF_RELU + 2 * REC_RELUBUF)    // 206592

__device__ __forceinline__ void lstm_xg_load(char* smraw, int buf, int n0, int t, int tid) {
    __half* dst = (__half*)(smraw + REC_OFF_XG + buf * REC_XGBUF);
#pragma unroll
    for (int it = 0; it < 2; it++) {
        int idx = it * 512 + tid;
        int r = idx >> 6, ck = idx & 63;
        cp16(dst + r * SXG_STRIDE + ck * 8,
             g_xg + ((size_t)(n0 + r) * Tt + t) * 512 + ck * 8);
    }
}

__global__ __launch_bounds__(512, 1) void lstm_kernel() {
    extern __shared__ char smraw[];
    __half* sW = (__half*)smraw;

    int tid = threadIdx.x;
    int w = tid >> 5, l = tid & 31;
    int dir = blockIdx.x & 1;
    int n0 = (blockIdx.x >> 1) * 16;

    {
        const uint4* src = (const uint4*)g_whh_h;
        uint4* dst = (uint4*)sW;
        for (int i = tid; i < 8704; i += 512) dst[i] = src[i];
    }
    for (int i = tid; i < 1088; i += 512) ((uint32_t*)(smraw + REC_OFF_H))[i] = 0u;

    const int lrow = (l & 7) + ((l >> 3) & 1) * 8;
    const int lcol = (l >> 4) * 8;
    const int g = l >> 2, tg = l & 3;
    const int wband = w * 8;     // 16 warps x 8 hidden cols

    uint32_t sWb = (uint32_t)__cvta_generic_to_shared(sW);
    uint32_t sHb = (uint32_t)__cvta_generic_to_shared(smraw + REC_OFF_H);

    const int sr = tid >> 5, sck = tid & 31;   // relu STG: 16 rows x 32 8B-chunks

    float c[2][2];
#pragma unroll
    for (int r2 = 0; r2 < 2; r2++) { c[r2][0] = 0.f; c[r2][1] = 0.f; }

    // prologue: prefetch xg for steps 0 and 1
    lstm_xg_load(smraw, 0, n0, dir ? 511 : 0, tid);
    cp_commit();
    lstm_xg_load(smraw, 1, n0, dir ? 510 : 1, tid);
    cp_commit();
    cp_wait1();
    __syncthreads();   // W, h0, sXG[0] all visible

    // hoist W_hh fragments (even warp keeps (r0,r2), odd keeps (r1,r3))
    uint32_t bf[4][8][2];
#pragma unroll
    for (int ks = 0; ks < 8; ks++) {
        int k0 = ks * 16;
#pragma unroll
        for (int gate = 0; gate < 4; gate++) {
            int j0p = gate * 128 + (w >> 1) * 16;
            uint32_t r0, r1, r2, r3;
            ldsm4(sWb + (uint32_t)(((j0p + lrow) * WPAD + k0 + lcol) << 1), r0, r1, r2, r3);
            if (w & 1) { bf[gate][ks][0] = r1; bf[gate][ks][1] = r3; }
            else       { bf[gate][ks][0] = r0; bf[gate][ks][1] = r2; }
        }
    }

    for (int step = 0; step < 512; step++) {
        int t = dir ? (511 - step) : step;

        // 1) coalesced STG of relu(h) for step-1
        if (step > 0) {
            int tp = dir ? (512 - step) : (step - 1);
            const __half* src =
                (const __half*)(smraw + REC_OFF_RELU + ((step + 1) & 1) * REC_RELUBUF);
            uint2 v = *(const uint2*)&src[sr * WPAD + sck * 4];
            *(uint2*)&g_hcat[((size_t)(n0 + sr) * Tt + tp) * 256 + dir * 128 + sck * 4] = v;
        }

        // 2) prefetch xg for step+2
        if (step + 2 < 512) {
            int tn = dir ? (509 - step) : (step + 2);
            lstm_xg_load(smraw, (step + 2) % 3, n0, tn, tid);
        }
        cp_commit();

        // 3) MMA with SPLIT accumulator chains (4-deep instead of 8-deep)
        uint32_t hcur = sHb + (uint32_t)(step & 1) * REC_HBUF;
        float d[4][4], dB[4][4];
#pragma unroll
        for (int gate = 0; gate < 4; gate++)
#pragma unroll
            for (int e = 0; e < 4; e++) { d[gate][e] = 0.f; dB[gate][e] = 0.f; }

#pragma unroll
        for (int ks = 0; ks < 8; ks++) {
            int k0 = ks * 16;
            uint32_t ah0, ah1, ah2, ah3;
            ldsm4(hcur + (uint32_t)((lrow * WPAD + k0 + lcol) << 1), ah0, ah1, ah2, ah3);
#pragma unroll
            for (int gate = 0; gate < 4; gate++)
                mma16816((ks & 1) ? dB[gate] : d[gate],
                         ah0, ah1, ah2, ah3, bf[gate][ks][0], bf[gate][ks][1]);
        }
#pragma unroll
        for (int gate = 0; gate < 4; gate++)
#pragma unroll
            for (int e = 0; e < 4; e++) d[gate][e] += dB[gate][e];

        // 4) activation
        const __half* sxg = (const __half*)(smraw + REC_OFF_XG + (step % 3) * REC_XGBUF);
        __half* hnxt = (__half*)(smraw + REC_OFF_H + ((step + 1) & 1) * REC_HBUF);
        __half* srel = (__half*)(smraw + REC_OFF_RELU + (step & 1) * REC_RELUBUF);

#pragma unroll
        for (int r2 = 0; r2 < 2; r2++) {
            int m = g + r2 * 8;
            int col = wband + 2 * tg;
            float2 xi  = __half22float2(*(const __half2*)&sxg[m * SXG_STRIDE + col]);
            float2 xf  = __half22float2(*(const __half2*)&sxg[m * SXG_STRIDE + 128 + col]);
            float2 xgg = __half22float2(*(const __half2*)&sxg[m * SXG_STRIDE + 256 + col]);
            float2 xo  = __half22float2(*(const __half2*)&sxg[m * SXG_STRIDE + 384 + col]);
            float hv[2];
#pragma unroll
            for (int e = 0; e < 2; e++) {
                int fe = r2 * 2 + e;
                float iv = d[0][fe] + ((const float*)&xi)[e];
                float fv = d[1][fe] + ((const float*)&xf)[e];
                float gv = d[2][fe] + ((const float*)&xgg)[e];
                float ov = d[3][fe] + ((const float*)&xo)[e];
                float cn = sigm_a(fv) * c[r2][e] + sigm_a(iv) * tanh_a(gv);
                c[r2][e] = cn;
                hv[e] = sigm_a(ov) * tanh_a(cn);
            }
            *(__half2*)&hnxt[m * WPAD + col] = __floats2half2_rn(hv[0], hv[1]);
            *(__half2*)&srel[m * WPAD + col] =
                __floats2half2_rn(fmaxf(hv[0], 0.f), fmaxf(hv[1], 0.f));
        }

        // 5) drain step+1's cp group, single per-step barrier
        cp_wait1();
        __syncthreads();
    }

    // final relu tile (step 511)
    {
        int tp = dir ? 0 : 511;
        const __half* src = (const __half*)(smraw + REC_OFF_RELU + 1 * REC_RELUBUF);
        uint2 v = *(const uint2*)&src[sr * WPAD + sck * 4];
        *(uint2*)&g_hcat[((size_t)(n0 + sr) * Tt + tp) * 256 + dir * 128 + sck * 4] = v;
    }
}

// ---------------- K3: decoder (persistent, tensor-core, direct fp16 tiles) — unchanged ----------------
#define DEC_OFF_T0  67584
#define DEC_TBUF    33792
#define DEC_OFF_PART (DEC_OFF_T0 + 2 * DEC_TBUF)
#define DEC_SMEM    (DEC_OFF_PART + 64 * 17 * 4)

__device__ __forceinline__ void dec_load_tile(char* smraw, int buf, int blk, int tid) {
    __half* dst = (__half*)(smraw + DEC_OFF_T0 + buf * DEC_TBUF);
    size_t row0 = (size_t)blk * 64;
#pragma unroll
    for (int it = 0; it < 16; it++) {
        int idx = it * 128 + tid;
        int r = idx >> 5, ck = idx & 31;
        cp16(dst + r * 264 + ck * 8, g_hcat + (row0 + r) * 256 + ck * 8);
    }
}

__global__ __launch_bounds__(128, 1) void decoder_kernel(
    const float* __restrict__ d1b, const float* __restrict__ d2w,
    const float* __restrict__ d2b, float* __restrict__ out) {
    extern __shared__ char smraw[];
    __half* sB = (__half*)smraw;
    float* sPart = (float*)(smraw + DEC_OFF_PART);

    int tid = threadIdx.x, w = tid >> 5, l = tid & 31;

    for (int i = tid; i < 4224; i += 128) cp16(((uint4*)sB) + i, ((const uint4*)g_dec1h) + i);
    cp_commit();

    const int lrow = (l & 7) + ((l >> 3) & 1) * 8;
    const int lcol = (l >> 4) * 8;
    const int jw = w * 32;
    const int g = l >> 2, tg = l & 3;
    uint32_t sBb = (uint32_t)__cvta_generic_to_shared(sB);
    uint32_t sTb = (uint32_t)__cvta_generic_to_shared(smraw + DEC_OFF_T0);

    float b1v[4][2], w2v[4][2];
#pragma unroll
    for (int nt = 0; nt < 4; nt++)
#pragma unroll
        for (int e = 0; e < 2; e++) {
            int col = jw + nt * 8 + 2 * tg + e;
            b1v[nt][e] = d1b[col];
            w2v[nt][e] = d2w[col];
        }
    float outb = d2b[0];
    cp_wait0();

    int blk = blockIdx.x;
    int buf = 0;
    dec_load_tile(smraw, buf, blk, tid);
    cp_commit();

    for (; blk < NTT / 64; blk += gridDim.x) {
        int nxt = blk + gridDim.x;
        if (nxt < NTT / 64) {
            dec_load_tile(smraw, buf ^ 1, nxt, tid);
            cp_commit();
            cp_wait1();
        } else {
            cp_wait0();
        }
        __syncthreads();

        uint32_t sAb = sTb + (uint32_t)buf * DEC_TBUF;
        int row0 = blk * 64;
#pragma unroll
        for (int mt = 0; mt < 4; mt++) {
            float d[4][4];
#pragma unroll
            for (int nt = 0; nt < 4; nt++)
#pragma unroll
                for (int e = 0; e < 4; e++) d[nt][e] = 0.f;
#pragma unroll
            for (int ks = 0; ks < 16; ks++) {
                uint32_t aoff = (uint32_t)(((mt * 16 + lrow) * 264 + ks * 16 + lcol) << 1);
                uint32_t ah0, ah1, ah2, ah3;
                ldsm4(sAb + aoff, ah0, ah1, ah2, ah3);
#pragma unroll
                for (int np = 0; np < 2; np++) {
                    uint32_t boff = (uint32_t)(((jw + np * 16 + lrow) * 264 + ks * 16 + lcol) << 1);
                    uint32_t b0, b1, b2, b3;
                    ldsm4(sBb + boff, b0, b1, b2, b3);
                    mma16816(d[2 * np],     ah0, ah1, ah2, ah3, b0, b2);
                    mma16816(d[2 * np + 1], ah0, ah1, ah2, ah3, b1, b3);
                }
            }
            float p0 = 0.f, p1 = 0.f;
#pragma unroll
            for (int nt = 0; nt < 4; nt++) {
                p0 += fmaxf(d[nt][0] + b1v[nt][0], 0.f) * w2v[nt][0];
                p0 += fmaxf(d[nt][1] + b1v[nt][1], 0.f) * w2v[nt][1];
                p1 += fmaxf(d[nt][2] + b1v[nt][0], 0.f) * w2v[nt][0];
                p1 += fmaxf(d[nt][3] + b1v[nt][1], 0.f) * w2v[nt][1];
            }
            sPart[(mt * 16 + g) * 17 + w * 4 + tg]     = p0;
            sPart[(mt * 16 + g + 8) * 17 + w * 4 + tg] = p1;
        }
        __syncthreads();

        if (tid < 64) {
            float s = 0.f;
#pragma unroll
            for (int q = 0; q < 16; q++) s += sPart[tid * 17 + q];
            out[row0 + tid] = s + outb;
        }
        __syncthreads();
        buf ^= 1;
    }
}

// ---------------- launch ----------------
extern "C" void kernel_launch(void* const* d_in, const int* in_sizes, int n_in,
                              void* d_out, int out_size) {
    (void)in_sizes; (void)n_in; (void)out_size;
    const float* x    = (const float*)d_in[0];
    const float* e1w  = (const float*)d_in[1];
    const float* e1b  = (const float*)d_in[2];
    const float* e2w  = (const float*)d_in[3];
    const float* e2b  = (const float*)d_in[4];
    const float* wih  = (const float*)d_in[5];
    const float* whh  = (const float*)d_in[6];
    const float* d1w  = (const float*)d_in[7];
    const float* d1b  = (const float*)d_in[8];
    const float* d2w  = (const float*)d_in[9];
    const float* d2b  = (const float*)d_in[10];
    float* out = (float*)d_out;

    static bool attr_done = false;
    if (!attr_done) {
        cudaFuncSetAttribute(encoder_kernel, cudaFuncAttributeMaxDynamicSharedMemorySize, ENC_SMEM);
        cudaFuncSetAttribute(lstm_kernel, cudaFuncAttributeMaxDynamicSharedMemorySize, REC_SMEM);
        cudaFuncSetAttribute(decoder_kernel, cudaFuncAttributeMaxDynamicSharedMemorySize, DEC_SMEM);
        attr_done = true;
    }

    prep_kernel<<<662, 256>>>(wih, whh, e2w, e2b, d1w);
    encoder_kernel<<<148, 256, ENC_SMEM>>>(x, e1w, e1b);
    lstm_kernel<<<128, 512, REC_SMEM>>>();
    decoder_kernel<<<148, 128, DEC_SMEM>>>(d1b, d2w, d2b, out);
}

// round 13
// speedup vs baseline: 1.1262x; 1.1262x over previous
#include <cuda_runtime.h>
#include <cuda_fp16.h>
#include <cstdint>

#define Nn 1024
#define Tt 512
#define Hh 128
#define Gg 512
#define NTT (Nn*Tt)
#define WPAD 136

// ---------------- device scratch ----------------
__device__ __half g_xg[(size_t)NTT * Gg];     // 512 MB fp16: xg = F1 @ M^T + bxg
__device__ __half g_hcat[(size_t)NTT * 256];  // 256 MB fp16: relu(h) [row][fw128|bw128]
__device__ __half g_whh_h[512 * WPAD];        // fp16 w_hh [j][k] padded
__device__ __half g_M_h[512 * WPAD];          // fp16 M = wih@e2w  [j][h] padded
__device__ float  g_bxg[512];                 // wih @ b2
__device__ __half g_dec1h[128 * 264];         // fp16 dec1 [o][k] padded (k stride 264)

__device__ __forceinline__ float tanh_a(float x) {
    float y; asm("tanh.approx.f32 %0, %1;" : "=f"(y) : "f"(x)); return y;
}
__device__ __forceinline__ float sigm_a(float x) {
    return fmaf(tanh_a(0.5f * x), 0.5f, 0.5f);
}

__device__ __forceinline__ void cp16(void* smem_dst, const void* gsrc) {
    unsigned s = (unsigned)__cvta_generic_to_shared(smem_dst);
    asm volatile("cp.async.ca.shared.global [%0], [%1], 16;" :: "r"(s), "l"(gsrc));
}
__device__ __forceinline__ void cp_commit() { asm volatile("cp.async.commit_group;"); }
__device__ __forceinline__ void cp_wait1()  { asm volatile("cp.async.wait_group 1;"); }
__device__ __forceinline__ void cp_wait0()  { asm volatile("cp.async.wait_group 0;"); }

__device__ __forceinline__ void ldsm4(uint32_t addr, uint32_t& r0, uint32_t& r1,
                                      uint32_t& r2, uint32_t& r3) {
    asm volatile("ldmatrix.sync.aligned.m8n8.x4.shared.b16 {%0,%1,%2,%3}, [%4];"
                 : "=r"(r0), "=r"(r1), "=r"(r2), "=r"(r3) : "r"(addr));
}
__device__ __forceinline__ void mma16816(float* d, uint32_t a0, uint32_t a1, uint32_t a2,
                                         uint32_t a3, uint32_t b0, uint32_t b1) {
    asm volatile(
        "mma.sync.aligned.m16n8k16.row.col.f32.f16.f16.f32 "
        "{%0,%1,%2,%3}, {%4,%5,%6,%7}, {%8,%9}, {%0,%1,%2,%3};"
        : "+f"(d[0]), "+f"(d[1]), "+f"(d[2]), "+f"(d[3])
        : "r"(a0), "r"(a1), "r"(a2), "r"(a3), "r"(b0), "r"(b1));
}

// ---------------- K0: weight prep ----------------
__global__ void prep_kernel(const float* __restrict__ wih, const float* __restrict__ whh,
                            const float* __restrict__ e2w, const float* __restrict__ e2b,
                            const float* __restrict__ dec1) {
    int i = blockIdx.x * blockDim.x + threadIdx.x;
    if (i < 65536) {
        int j = i >> 7, h = i & 127;
        float s = 0.f;
#pragma unroll 4
        for (int o = 0; o < 128; o++) s += wih[j * 128 + o] * e2w[o * 128 + h];
        g_M_h[j * WPAD + h] = __float2half(s);
    } else if (i < 66048) {
        int j = i - 65536;
        float s = 0.f;
#pragma unroll 4
        for (int o = 0; o < 128; o++) s += e2b[o] * wih[j * 128 + o];
        g_bxg[j] = s;
    } else if (i < 135680) {
        int p = i - 66048;
        int j = p / WPAD, k = p % WPAD;
        g_whh_h[p] = (k < 128) ? __float2half(whh[j * 128 + k]) : __float2half(0.f);
    } else if (i < 169472) {
        int p = i - 135680;
        int j = p / 264, k = p % 264;
        g_dec1h[p] = (k < 256) ? __float2half(dec1[j * 256 + k]) : __float2half(0.f);
    }
}

// ---------------- K1: encoder (persistent, 256 thr, reg-resident M) ----------------
#define ENC_OFF_AHI 139264
#define ENC_OFF_BXG 156672
#define ENC_OFF_E1W 158720
#define ENC_OFF_E1B 159744
#define ENC_SMEM    160256
__global__ __launch_bounds__(256, 1) void encoder_kernel(
    const float* __restrict__ x, const float* __restrict__ e1w,
    const float* __restrict__ e1b) {
    extern __shared__ char smraw[];
    __half* sM   = (__half*)smraw;
    __half* sAhi = (__half*)(smraw + ENC_OFF_AHI);
    float*  sBxg = (float*)(smraw + ENC_OFF_BXG);
    float*  sE1w = (float*)(smraw + ENC_OFF_E1W);
    float*  sE1b = (float*)(smraw + ENC_OFF_E1B);

    int tid = threadIdx.x, w = tid >> 5, l = tid & 31;

    for (int i = tid; i < 8704; i += 256) cp16(((uint4*)sM) + i, ((const uint4*)g_M_h) + i);
    cp_commit();
    for (int i = tid; i < 512; i += 256) sBxg[i] = g_bxg[i];
    if (tid < 256) sE1w[tid] = e1w[tid];
    if (tid < 128) sE1b[tid] = e1b[tid];
    cp_wait0();
    __syncthreads();

    const int lrow = (l & 7) + ((l >> 3) & 1) * 8;
    const int lcol = (l >> 4) * 8;
    const int jw = w * 64;
    const int g = l >> 2, tg = l & 3;
    uint32_t sMb   = (uint32_t)__cvta_generic_to_shared(sM);
    uint32_t sAhib = (uint32_t)__cvta_generic_to_shared(sAhi);

    // hoist loop-invariant M fragments: [np][ks][4]
    uint32_t bfE[4][8][4];
#pragma unroll
    for (int ks = 0; ks < 8; ks++)
#pragma unroll
        for (int np = 0; np < 4; np++) {
            uint32_t boff = (uint32_t)(((jw + np * 16 + lrow) * WPAD + ks * 16 + lcol) << 1);
            ldsm4(sMb + boff, bfE[np][ks][0], bfE[np][ks][1], bfE[np][ks][2], bfE[np][ks][3]);
        }

    const int fr = tid >> 2, fh0 = (tid & 3) * 32;

    for (int blk = blockIdx.x; blk < NTT / 64; blk += gridDim.x) {
        int row0 = blk * 64;
        float x0 = x[(size_t)(row0 + fr) * 2];
        float x1 = x[(size_t)(row0 + fr) * 2 + 1];
#pragma unroll
        for (int hh = 0; hh < 32; hh += 2) {
            int h = fh0 + hh;
            float v0 = fmaxf(sE1w[2 * h]     * x0 + sE1w[2 * h + 1] * x1 + sE1b[h], 0.f);
            float v1 = fmaxf(sE1w[2 * h + 2] * x0 + sE1w[2 * h + 3] * x1 + sE1b[h + 1], 0.f);
            *(__half2*)&sAhi[fr * WPAD + h] = __floats2half2_rn(v0, v1);
        }
        __syncthreads();

#pragma unroll
        for (int mt = 0; mt < 4; mt++) {
            float d[8][4];
#pragma unroll
            for (int nt = 0; nt < 8; nt++)
#pragma unroll
                for (int e = 0; e < 4; e++) d[nt][e] = 0.f;
#pragma unroll
            for (int ks = 0; ks < 8; ks++) {
                uint32_t aoff = (uint32_t)(((mt * 16 + lrow) * WPAD + ks * 16 + lcol) << 1);
                uint32_t ah0, ah1, ah2, ah3;
                ldsm4(sAhib + aoff, ah0, ah1, ah2, ah3);
#pragma unroll
                for (int np = 0; np < 4; np++) {
                    mma16816(d[2 * np],     ah0, ah1, ah2, ah3, bfE[np][ks][0], bfE[np][ks][2]);
                    mma16816(d[2 * np + 1], ah0, ah1, ah2, ah3, bfE[np][ks][1], bfE[np][ks][3]);
                }
            }
            size_t rb0 = (size_t)(row0 + mt * 16 + g) * 512;
            size_t rb1 = rb0 + (size_t)8 * 512;
#pragma unroll
            for (int nt = 0; nt < 8; nt++) {
                int col = jw + nt * 8 + 2 * tg;
                float b0v = sBxg[col], b1v = sBxg[col + 1];
                *(__half2*)&g_xg[rb0 + col] = __floats2half2_rn(d[nt][0] + b0v, d[nt][1] + b1v);
                *(__half2*)&g_xg[rb1 + col] = __floats2half2_rn(d[nt][2] + b0v, d[nt][3] + b1v);
            }
        }
        __syncthreads();
    }
}

// ---------------- K2: bidirectional LSTM — R11 exact (512 thr, reg-resident W) ----------------
#define REC_OFF_H    139264
#define REC_HBUF     4352
#define REC_OFF_XG   (REC_OFF_H + 2 * REC_HBUF)          // 147968
#define REC_XGBUF    16640
#define SXG_STRIDE   520
#define REC_OFF_RELU (REC_OFF_XG + 3 * REC_XGBUF)        // 197888
#define REC_RELUBUF  4352
#define REC_SMEM     (REC_OFF_RELU + 2 * REC_RELUBUF)    // 206592

__device__ __forceinline__ void lstm_xg_load(char* smraw, int buf, int n0, int t, int tid) {
    __half* dst = (__half*)(smraw + REC_OFF_XG + buf * REC_XGBUF);
#pragma unroll
    for (int it = 0; it < 2; it++) {
        int idx = it * 512 + tid;
        int r = idx >> 6, ck = idx & 63;
        cp16(dst + r * SXG_STRIDE + ck * 8,
             g_xg + ((size_t)(n0 + r) * Tt + t) * 512 + ck * 8);
    }
}

__global__ __launch_bounds__(512, 1) void lstm_kernel() {
    extern __shared__ char smraw[];
    __half* sW = (__half*)smraw;

    int tid = threadIdx.x;
    int w = tid >> 5, l = tid & 31;
    int dir = blockIdx.x & 1;
    int n0 = (blockIdx.x >> 1) * 16;

    {
        const uint4* src = (const uint4*)g_whh_h;
        uint4* dst = (uint4*)sW;
        for (int i = tid; i < 8704; i += 512) dst[i] = src[i];
    }
    for (int i = tid; i < 1088; i += 512) ((uint32_t*)(smraw + REC_OFF_H))[i] = 0u;

    const int lrow = (l & 7) + ((l >> 3) & 1) * 8;
    const int lcol = (l >> 4) * 8;
    const int g = l >> 2, tg = l & 3;
    const int wband = w * 8;     // 16 warps x 8 hidden cols

    uint32_t sWb = (uint32_t)__cvta_generic_to_shared(sW);
    uint32_t sHb = (uint32_t)__cvta_generic_to_shared(smraw + REC_OFF_H);

    const int sr = tid >> 5, sck = tid & 31;

    float c[2][2];
#pragma unroll
    for (int r2 = 0; r2 < 2; r2++) { c[r2][0] = 0.f; c[r2][1] = 0.f; }

    lstm_xg_load(smraw, 0, n0, dir ? 511 : 0, tid);
    cp_commit();
    lstm_xg_load(smraw, 1, n0, dir ? 510 : 1, tid);
    cp_commit();
    cp_wait1();
    __syncthreads();

    uint32_t bf[4][8][2];
#pragma unroll
    for (int ks = 0; ks < 8; ks++) {
        int k0 = ks * 16;
#pragma unroll
        for (int gate = 0; gate < 4; gate++) {
            int j0p = gate * 128 + (w >> 1) * 16;
            uint32_t r0, r1, r2, r3;
            ldsm4(sWb + (uint32_t)(((j0p + lrow) * WPAD + k0 + lcol) << 1), r0, r1, r2, r3);
            if (w & 1) { bf[gate][ks][0] = r1; bf[gate][ks][1] = r3; }
            else       { bf[gate][ks][0] = r0; bf[gate][ks][1] = r2; }
        }
    }

    for (int step = 0; step < 512; step++) {
        int t = dir ? (511 - step) : step;

        if (step > 0) {
            int tp = dir ? (512 - step) : (step - 1);
            const __half* src =
                (const __half*)(smraw + REC_OFF_RELU + ((step + 1) & 1) * REC_RELUBUF);
            uint2 v = *(const uint2*)&src[sr * WPAD + sck * 4];
            *(uint2*)&g_hcat[((size_t)(n0 + sr) * Tt + tp) * 256 + dir * 128 + sck * 4] = v;
        }

        if (step + 2 < 512) {
            int tn = dir ? (509 - step) : (step + 2);
            lstm_xg_load(smraw, (step + 2) % 3, n0, tn, tid);
        }
        cp_commit();

        uint32_t hcur = sHb + (uint32_t)(step & 1) * REC_HBUF;
        float d[4][4];
#pragma unroll
        for (int gate = 0; gate < 4; gate++)
#pragma unroll
            for (int e = 0; e < 4; e++) d[gate][e] = 0.f;

#pragma unroll
        for (int ks = 0; ks < 8; ks++) {
            int k0 = ks * 16;
            uint32_t ah0, ah1, ah2, ah3;
            ldsm4(hcur + (uint32_t)((lrow * WPAD + k0 + lcol) << 1), ah0, ah1, ah2, ah3);
#pragma unroll
            for (int gate = 0; gate < 4; gate++)
                mma16816(d[gate], ah0, ah1, ah2, ah3, bf[gate][ks][0], bf[gate][ks][1]);
        }

        const __half* sxg = (const __half*)(smraw + REC_OFF_XG + (step % 3) * REC_XGBUF);
        __half* hnxt = (__half*)(smraw + REC_OFF_H + ((step + 1) & 1) * REC_HBUF);
        __half* srel = (__half*)(smraw + REC_OFF_RELU + (step & 1) * REC_RELUBUF);

#pragma unroll
        for (int r2 = 0; r2 < 2; r2++) {
            int m = g + r2 * 8;
            int col = wband + 2 * tg;
            float2 xi  = __half22float2(*(const __half2*)&sxg[m * SXG_STRIDE + col]);
            float2 xf  = __half22float2(*(const __half2*)&sxg[m * SXG_STRIDE + 128 + col]);
            float2 xgg = __half22float2(*(const __half2*)&sxg[m * SXG_STRIDE + 256 + col]);
            float2 xo  = __half22float2(*(const __half2*)&sxg[m * SXG_STRIDE + 384 + col]);
            float hv[2];
#pragma unroll
            for (int e = 0; e < 2; e++) {
                int fe = r2 * 2 + e;
                float iv = d[0][fe] + ((const float*)&xi)[e];
                float fv = d[1][fe] + ((const float*)&xf)[e];
                float gv = d[2][fe] + ((const float*)&xgg)[e];
                float ov = d[3][fe] + ((const float*)&xo)[e];
                float cn = sigm_a(fv) * c[r2][e] + sigm_a(iv) * tanh_a(gv);
                c[r2][e] = cn;
                hv[e] = sigm_a(ov) * tanh_a(cn);
            }
            *(__half2*)&hnxt[m * WPAD + col] = __floats2half2_rn(hv[0], hv[1]);
            *(__half2*)&srel[m * WPAD + col] =
                __floats2half2_rn(fmaxf(hv[0], 0.f), fmaxf(hv[1], 0.f));
        }

        cp_wait1();
        __syncthreads();
    }

    {
        int tp = dir ? 0 : 511;
        const __half* src = (const __half*)(smraw + REC_OFF_RELU + 1 * REC_RELUBUF);
        uint2 v = *(const uint2*)&src[sr * WPAD + sck * 4];
        *(uint2*)&g_hcat[((size_t)(n0 + sr) * Tt + tp) * 256 + dir * 128 + sck * 4] = v;
    }
}

// ---------------- K3: decoder (persistent, reg-resident dec1) ----------------
#define DEC_OFF_T0  67584
#define DEC_TBUF    33792
#define DEC_OFF_PART (DEC_OFF_T0 + 2 * DEC_TBUF)
#define DEC_SMEM    (DEC_OFF_PART + 64 * 17 * 4)

__device__ __forceinline__ void dec_load_tile(char* smraw, int buf, int blk, int tid) {
    __half* dst = (__half*)(smraw + DEC_OFF_T0 + buf * DEC_TBUF);
    size_t row0 = (size_t)blk * 64;
#pragma unroll
    for (int it = 0; it < 16; it++) {
        int idx = it * 128 + tid;
        int r = idx >> 5, ck = idx & 31;
        cp16(dst + r * 264 + ck * 8, g_hcat + (row0 + r) * 256 + ck * 8);
    }
}

__global__ __launch_bounds__(128, 1) void decoder_kernel(
    const float* __restrict__ d1b, const float* __restrict__ d2w,
    const float* __restrict__ d2b, float* __restrict__ out) {
    extern __shared__ char smraw[];
    __half* sB = (__half*)smraw;
    float* sPart = (float*)(smraw + DEC_OFF_PART);

    int tid = threadIdx.x, w = tid >> 5, l = tid & 31;

    for (int i = tid; i < 4224; i += 128) cp16(((uint4*)sB) + i, ((const uint4*)g_dec1h) + i);
    cp_commit();

    const int lrow = (l & 7) + ((l >> 3) & 1) * 8;
    const int lcol = (l >> 4) * 8;
    const int jw = w * 32;
    const int g = l >> 2, tg = l & 3;
    uint32_t sBb = (uint32_t)__cvta_generic_to_shared(sB);
    uint32_t sTb = (uint32_t)__cvta_generic_to_shared(smraw + DEC_OFF_T0);

    float b1v[4][2], w2v[4][2];
#pragma unroll
    for (int nt = 0; nt < 4; nt++)
#pragma unroll
        for (int e = 0; e < 2; e++) {
            int col = jw + nt * 8 + 2 * tg + e;
            b1v[nt][e] = d1b[col];
            w2v[nt][e] = d2w[col];
        }
    float outb = d2b[0];
    cp_wait0();
    __syncthreads();   // sB visible to all lanes before hoist ldsm

    // hoist loop-invariant dec1 fragments: [np][ks][4]
    uint32_t bfD[2][16][4];
#pragma unroll
    for (int ks = 0; ks < 16; ks++)
#pragma unroll
        for (int np = 0; np < 2; np++) {
            uint32_t boff = (uint32_t)(((jw + np * 16 + lrow) * 264 + ks * 16 + lcol) << 1);
            ldsm4(sBb + boff, bfD[np][ks][0], bfD[np][ks][1], bfD[np][ks][2], bfD[np][ks][3]);
        }

    int blk = blockIdx.x;
    int buf = 0;
    dec_load_tile(smraw, buf, blk, tid);
    cp_commit();

    for (; blk < NTT / 64; blk += gridDim.x) {
        int nxt = blk + gridDim.x;
        if (nxt < NTT / 64) {
            dec_load_tile(smraw, buf ^ 1, nxt, tid);
            cp_commit();
            cp_wait1();
        } else {
            cp_wait0();
        }
        __syncthreads();

        uint32_t sAb = sTb + (uint32_t)buf * DEC_TBUF;
        int row0 = blk * 64;
#pragma unroll
        for (int mt = 0; mt < 4; mt++) {
            float d[4][4];
#pragma unroll
            for (int nt = 0; nt < 4; nt++)
#pragma unroll
                for (int e = 0; e < 4; e++) d[nt][e] = 0.f;
#pragma unroll
            for (int ks = 0; ks < 16; ks++) {
                uint32_t aoff = (uint32_t)(((mt * 16 + lrow) * 264 + ks * 16 + lcol) << 1);
                uint32_t ah0, ah1, ah2, ah3;
                ldsm4(sAb + aoff, ah0, ah1, ah2, ah3);
#pragma unroll
                for (int np = 0; np < 2; np++) {
                    mma16816(d[2 * np],     ah0, ah1, ah2, ah3, bfD[np][ks][0], bfD[np][ks][2]);
                    mma16816(d[2 * np + 1], ah0, ah1, ah2, ah3, bfD[np][ks][1], bfD[np][ks][3]);
                }
            }
            float p0 = 0.f, p1 = 0.f;
#pragma unroll
            for (int nt = 0; nt < 4; nt++) {
                p0 += fmaxf(d[nt][0] + b1v[nt][0], 0.f) * w2v[nt][0];
                p0 += fmaxf(d[nt][1] + b1v[nt][1], 0.f) * w2v[nt][1];
                p1 += fmaxf(d[nt][2] + b1v[nt][0], 0.f) * w2v[nt][0];
                p1 += fmaxf(d[nt][3] + b1v[nt][1], 0.f) * w2v[nt][1];
            }
            sPart[(mt * 16 + g) * 17 + w * 4 + tg]     = p0;
            sPart[(mt * 16 + g + 8) * 17 + w * 4 + tg] = p1;
        }
        __syncthreads();

        if (tid < 64) {
            float s = 0.f;
#pragma unroll
            for (int q = 0; q < 16; q++) s += sPart[tid * 17 + q];
            out[row0 + tid] = s + outb;
        }
        __syncthreads();
        buf ^= 1;
    }
}

// ---------------- launch ----------------
extern "C" void kernel_launch(void* const* d_in, const int* in_sizes, int n_in,
                              void* d_out, int out_size) {
    (void)in_sizes; (void)n_in; (void)out_size;
    const float* x    = (const float*)d_in[0];
    const float* e1w  = (const float*)d_in[1];
    const float* e1b  = (const float*)d_in[2];
    const float* e2w  = (const float*)d_in[3];
    const float* e2b  = (const float*)d_in[4];
    const float* wih  = (const float*)d_in[5];
    const float* whh  = (const float*)d_in[6];
    const float* d1w  = (const float*)d_in[7];
    const float* d1b  = (const float*)d_in[8];
    const float* d2w  = (const float*)d_in[9];
    const float* d2b  = (const float*)d_in[10];
    float* out = (float*)d_out;

    static bool attr_done = false;
    if (!attr_done) {
        cudaFuncSetAttribute(encoder_kernel, cudaFuncAttributeMaxDynamicSharedMemorySize, ENC_SMEM);
        cudaFuncSetAttribute(lstm_kernel, cudaFuncAttributeMaxDynamicSharedMemorySize, REC_SMEM);
        cudaFuncSetAttribute(decoder_kernel, cudaFuncAttributeMaxDynamicSharedMemorySize, DEC_SMEM);
        attr_done = true;
    }

    prep_kernel<<<662, 256>>>(wih, whh, e2w, e2b, d1w);
    encoder_kernel<<<148, 256, ENC_SMEM>>>(x, e1w, e1b);
    lstm_kernel<<<128, 512, REC_SMEM>>>();
    decoder_kernel<<<148, 128, DEC_SMEM>>>(d1b, d2w, d2b, out);
}